// round 6
// baseline (speedup 1.0000x reference)
#include <cuda_runtime.h>
#include <cuda_bf16.h>

// AdEx neuron sim, sm_103a. Round 6.
// R5 numerics frozen (reference-ordered update, __expf) — rel_err 1.6e-8.
// New: perfectly balanced grid. 296 blocks (=2 per SM on 148 SMs) x 352 threads;
// each block owns neuron slice [b*N/296, (b+1)*N/296) => every SM gets ~676
// neurons. Removes the 3-vs-2 blocks/SM imbalance of the ceil-grid launch
// (391 blocks -> 95 SMs did 50% more work than the other 53).

#define UNROLL 16
#define GRID_BLOCKS 296
#define BLOCK_THREADS 352

#define C_EL        (-70.6e-3f)
#define C_VT        (-50.4e-3f)
#define C_INVDELT   (500.0f)                 // 1 / DELTAT
#define C_GLDT      (6.0e-11f)               // GL * DELTAT
#define C_GL        (30.0e-9f)
#define C_DTCM      (3.5587188612099645e6f)  // DT / CM
#define C_DTTAUW    (6.944444444444445e-3f)  // DT / TAUW
#define C_A         (4.0e-9f)
#define C_B         (0.0805e-9f)
#define C_REFSTEPS  2

// Reference expression structure (do not re-associate); only exp is approx.
__device__ __forceinline__ void adex_step(float It, float& v, float& c, int& ref,
                                          float& v_out) {
    bool  in_ref = ref > 0;
    float v_eff  = in_ref ? C_EL : v;

    float arg = fminf((v_eff - C_VT) * C_INVDELT, 15.0f);
    float ex  = C_GLDT * __expf(arg);        // FMUL + MUFU.EX2 + FMUL
    float dv  = C_DTCM * (-C_GL * (v_eff - C_EL) + ex - c + It);
    float v_new = in_ref ? C_EL : (v_eff + dv);

    float c_new = c + C_DTTAUW * (C_A * (v_eff - C_EL) - c);

    bool spike = v_new >= C_VT;
    v   = spike ? C_EL : v_new;
    c   = spike ? (c_new + C_B) : c_new;
    ref = spike ? C_REFSTEPS : max(ref - 1, 0);
    v_out = v;
}

template<int N_STATIC>
__device__ __forceinline__ void adex_body(
    const float* __restrict__ I, const float* __restrict__ v0,
    const float* __restrict__ c0, const int* __restrict__ ref0,
    float* __restrict__ out, int T, int N, int n)
{
    float v   = v0[n];
    float c   = c0[n];
    int   ref = ref0[n];

    const float* Ip = I + n;
    float*       Op = out + n;

    // prime rows 0..UNROLL-1
    float buf[UNROLL];
    #pragma unroll
    for (int u = 0; u < UNROLL; ++u)
        buf[u] = (u < T) ? __ldcs(Ip + (size_t)u * N) : 0.0f;

    // steady state: prefetch row t+UNROLL+u always in range (no predicates)
    int t = 0;
    for (; t + 2 * UNROLL <= T; t += UNROLL) {
        const float* Ipn = Ip + (size_t)(t + UNROLL) * N;  // +u*N fold to immediates
        float*       Opt = Op + (size_t)t * N;
        #pragma unroll
        for (int u = 0; u < UNROLL; ++u) {
            float It = buf[u];
            buf[u] = __ldcs(Ipn + (size_t)u * N);
            float ov;
            adex_step(It, v, c, ref, ov);
            __stcs(Opt + (size_t)u * N, ov);
        }
    }

    // epilogue 1: consume resident rows, refill guarded
    #pragma unroll
    for (int u = 0; u < UNROLL; ++u) {
        int row = t + u;
        if (row < T) {
            float It = buf[u];
            int tt = row + UNROLL;
            float nx = (tt < T) ? __ldcs(Ip + (size_t)tt * N) : 0.0f;
            float ov;
            adex_step(It, v, c, ref, ov);
            __stcs(Op + (size_t)row * N, ov);
            buf[u] = nx;
        }
    }
    t += UNROLL;

    // epilogue 2: remaining < UNROLL rows
    #pragma unroll
    for (int u = 0; u < UNROLL; ++u) {
        int row = t + u;
        if (row < T) {
            float ov;
            adex_step(buf[u], v, c, ref, ov);
            __stcs(Op + (size_t)row * N, ov);
        }
    }
}

// Balanced kernel: block b owns neurons [b*N/G, (b+1)*N/G).
template<int N_STATIC>
__global__ void __launch_bounds__(BLOCK_THREADS) adex_balanced_kernel(
    const float* __restrict__ I, const float* __restrict__ v0,
    const float* __restrict__ c0, const int* __restrict__ ref0,
    float* __restrict__ out, int T, int N_rt)
{
    const int N = (N_STATIC > 0) ? N_STATIC : N_rt;
    const int G = gridDim.x;
    int b     = blockIdx.x;
    int start = (int)(((long long)b * N) / G);
    int end   = (int)(((long long)(b + 1) * N) / G);
    int n     = start + threadIdx.x;
    if (n >= end) return;

    adex_body<N_STATIC>(I, v0, c0, ref0, out, T, N, n);
}

// generic fallback (ceil grid), for unexpected shapes
__global__ void __launch_bounds__(256) adex_generic_kernel(
    const float* __restrict__ I, const float* __restrict__ v0,
    const float* __restrict__ c0, const int* __restrict__ ref0,
    float* __restrict__ out, int T, int N)
{
    int n = blockIdx.x * blockDim.x + threadIdx.x;
    if (n >= N) return;
    adex_body<0>(I, v0, c0, ref0, out, T, N, n);
}

extern "C" void kernel_launch(void* const* d_in, const int* in_sizes, int n_in,
                              void* d_out, int out_size)
{
    const float* I    = (const float*)d_in[0];
    const float* v0   = (const float*)d_in[1];
    const float* c0   = (const float*)d_in[2];
    const int*   ref0 = (const int*)  d_in[3];
    float*       out  = (float*)d_out;

    int N = in_sizes[1];
    int T = in_sizes[0] / N;

    if (N == 100000) {
        // 296 blocks = exactly 2 per SM; each block <= 338 neurons <= 352 threads
        adex_balanced_kernel<100000><<<GRID_BLOCKS, BLOCK_THREADS>>>(
            I, v0, c0, ref0, out, T, N);
    } else {
        int threads = 256;
        int blocks  = (N + threads - 1) / threads;
        adex_generic_kernel<<<blocks, threads>>>(I, v0, c0, ref0, out, T, N);
    }
}

// round 7
// speedup vs baseline: 1.0333x; 1.0333x over previous
#include <cuda_runtime.h>
#include <cuda_bf16.h>

// AdEx neuron sim, sm_103a. Round 7.
// R5 numerics frozen (reference-ordered update, __expf) — rel_err 1.6e-8.
// Changes vs R5 (best wall config): UNROLL 16 -> 32 (probe: is the 48% stall
// time load latency?), shared (v_eff - EL) subexpression (bit-identical),
// plain ceil grid 391x256 restored.

#define UNROLL 32

#define C_EL        (-70.6e-3f)
#define C_VT        (-50.4e-3f)
#define C_INVDELT   (500.0f)                 // 1 / DELTAT
#define C_GLDT      (6.0e-11f)               // GL * DELTAT
#define C_GL        (30.0e-9f)
#define C_DTCM      (3.5587188612099645e6f)  // DT / CM
#define C_DTTAUW    (6.944444444444445e-3f)  // DT / TAUW
#define C_A         (4.0e-9f)
#define C_B         (0.0805e-9f)
#define C_REFSTEPS  2

// Reference expression structure (do not re-associate); only exp is approx.
__device__ __forceinline__ void adex_step(float It, float& v, float& c, int& ref,
                                          float& v_out) {
    bool  in_ref = ref > 0;
    float v_eff  = in_ref ? C_EL : v;

    float ve  = v_eff - C_EL;                // shared by dv and c (same rounding)
    float arg = fminf((v_eff - C_VT) * C_INVDELT, 15.0f);
    float ex  = C_GLDT * __expf(arg);        // FMUL + MUFU.EX2 + FMUL
    float dv  = C_DTCM * (-C_GL * ve + ex - c + It);
    float v_new = in_ref ? C_EL : (v_eff + dv);

    float c_new = c + C_DTTAUW * (C_A * ve - c);

    bool spike = v_new >= C_VT;
    v   = spike ? C_EL : v_new;
    c   = spike ? (c_new + C_B) : c_new;
    ref = spike ? C_REFSTEPS : max(ref - 1, 0);
    v_out = v;
}

template<int N_STATIC>
__global__ void __launch_bounds__(256) adex_kernel(
    const float* __restrict__ I,    // [T, N]
    const float* __restrict__ v0,
    const float* __restrict__ c0,
    const int*   __restrict__ ref0,
    float*       __restrict__ out,  // [T, N]
    int T, int N_rt)
{
    const int N = (N_STATIC > 0) ? N_STATIC : N_rt;
    int n = blockIdx.x * blockDim.x + threadIdx.x;
    if (n >= N) return;

    float v   = v0[n];
    float c   = c0[n];
    int   ref = ref0[n];

    const float* Ip = I + n;
    float*       Op = out + n;

    // prime rows 0..UNROLL-1
    float buf[UNROLL];
    #pragma unroll
    for (int u = 0; u < UNROLL; ++u)
        buf[u] = (u < T) ? __ldcs(Ip + (size_t)u * N) : 0.0f;

    // steady state: prefetch row t+UNROLL+u always in range (no predicates)
    int t = 0;
    for (; t + 2 * UNROLL <= T; t += UNROLL) {
        const float* Ipn = Ip + (size_t)(t + UNROLL) * N;  // +u*N fold to immediates
        float*       Opt = Op + (size_t)t * N;
        #pragma unroll
        for (int u = 0; u < UNROLL; ++u) {
            float It = buf[u];
            buf[u] = __ldcs(Ipn + (size_t)u * N);
            float ov;
            adex_step(It, v, c, ref, ov);
            __stcs(Opt + (size_t)u * N, ov);
        }
    }

    // epilogue 1: consume resident rows t..t+UNROLL-1, refill guarded
    #pragma unroll
    for (int u = 0; u < UNROLL; ++u) {
        int row = t + u;
        if (row < T) {
            float It = buf[u];
            int tt = row + UNROLL;
            float nx = (tt < T) ? __ldcs(Ip + (size_t)tt * N) : 0.0f;
            float ov;
            adex_step(It, v, c, ref, ov);
            __stcs(Op + (size_t)row * N, ov);
            buf[u] = nx;
        }
    }
    t += UNROLL;

    // epilogue 2: remaining < UNROLL rows
    #pragma unroll
    for (int u = 0; u < UNROLL; ++u) {
        int row = t + u;
        if (row < T) {
            float ov;
            adex_step(buf[u], v, c, ref, ov);
            __stcs(Op + (size_t)row * N, ov);
        }
    }
}

extern "C" void kernel_launch(void* const* d_in, const int* in_sizes, int n_in,
                              void* d_out, int out_size)
{
    const float* I    = (const float*)d_in[0];
    const float* v0   = (const float*)d_in[1];
    const float* c0   = (const float*)d_in[2];
    const int*   ref0 = (const int*)  d_in[3];
    float*       out  = (float*)d_out;

    int N = in_sizes[1];
    int T = in_sizes[0] / N;

    int threads = 256;
    int blocks  = (N + threads - 1) / threads;

    if (N == 100000) {
        adex_kernel<100000><<<blocks, threads>>>(I, v0, c0, ref0, out, T, N);
    } else {
        adex_kernel<0><<<blocks, threads>>>(I, v0, c0, ref0, out, T, N);
    }
}

// round 8
// speedup vs baseline: 1.1065x; 1.0709x over previous
#include <cuda_runtime.h>
#include <cuda_bf16.h>

// AdEx neuron sim, sm_103a. Round 8.
// Issue-count diet: (1) v_eff select removed (invariant: v==EL while refractory),
// (2) refractory counter -> two rotated spike predicates (kills int pipeline),
// (3) GL*DELTAT folded into the ex2 exponent (exp term = FADD+FFMA+FMNMX+MUFU).
// dv / v update chain stays reference-ordered. UNROLL=16 (32 proven neutral).

#define UNROLL 16

#define C_EL        (-70.6e-3f)
#define C_VT        (-50.4e-3f)
#define C_GL        (30.0e-9f)
#define C_DTCM      (3.5587188612099645e6f)   // DT / CM
#define C_DTTAUW    (6.944444444444445e-3f)   // DT / TAUW
#define C_A         (4.0e-9f)
#define C_B         (0.0805e-9f)
// exp folding: GLDT*exp(min(d/DELTAT,15)) = 2^(min(d*500*log2e + log2(GLDT), clip))
#define C_YSLOPE    (721.3475204444817f)      // 500 * log2(e)
#define C_YBIAS     (-33.9562265429f)         // log2(GL*DELTAT) = log2(6e-11)
#define C_YCLIP     (-12.3158009296f)         // 15*log2(e) + C_YBIAS

// p1 = spiked last step, p2 = spiked two steps ago  (REF_STEPS = 2)
__device__ __forceinline__ void adex_step(float It, float& v, float& c,
                                          bool& p1, bool& p2, float& v_out) {
    bool in_ref = p1 | p2;

    float ve = v - C_EL;
    float d  = v - C_VT;                         // cancellation-free
    float y  = fminf(fmaf(d, C_YSLOPE, C_YBIAS), C_YCLIP);
    float E;                                      // = GL*DELTAT*exp(clipped arg)
    asm("ex2.approx.ftz.f32 %0, %1;" : "=f"(E) : "f"(y));

    // dv = DTCM * (-GL*ve + E - c + It); v_new = v + dv   (reference order)
    float s1 = fmaf(-C_GL, ve, E);
    float s2 = s1 - c;
    float s3 = s2 + It;
    float dv = C_DTCM * s3;
    float v_new = v + dv;

    bool spike = (v_new >= C_VT) & (!in_ref);

    float c_mid = fmaf(C_A, ve, -c);
    float c_new = fmaf(C_DTTAUW, c_mid, c);

    v = (spike | in_ref) ? C_EL : v_new;
    c = spike ? (c_new + C_B) : c_new;
    p2 = p1;
    p1 = spike;
    v_out = v;
}

template<int N_STATIC>
__global__ void __launch_bounds__(256) adex_kernel(
    const float* __restrict__ I,    // [T, N]
    const float* __restrict__ v0,
    const float* __restrict__ c0,
    const int*   __restrict__ ref0,
    float*       __restrict__ out,  // [T, N]
    int T, int N_rt)
{
    const int N = (N_STATIC > 0) ? N_STATIC : N_rt;
    int n = blockIdx.x * blockDim.x + threadIdx.x;
    if (n >= N) return;

    float v   = v0[n];
    float c   = c0[n];
    int   ref = ref0[n];
    bool  p1  = (ref > 1);        // >=2 steps left  <=> spiked last step
    bool  p2  = (ref == 1);       // exactly 1 left  <=> spiked two steps ago
    if (p1 | p2) v = C_EL;        // establish invariant (reference discards v anyway)

    const float* Ip = I + n;
    float*       Op = out + n;

    float buf[UNROLL];
    #pragma unroll
    for (int u = 0; u < UNROLL; ++u)
        buf[u] = (u < T) ? __ldcs(Ip + (size_t)u * N) : 0.0f;

    int t = 0;
    for (; t + 2 * UNROLL <= T; t += UNROLL) {
        const float* Ipn = Ip + (size_t)(t + UNROLL) * N;  // +u*N fold to immediates
        float*       Opt = Op + (size_t)t * N;
        #pragma unroll
        for (int u = 0; u < UNROLL; ++u) {
            float It = buf[u];
            buf[u] = __ldcs(Ipn + (size_t)u * N);
            float ov;
            adex_step(It, v, c, p1, p2, ov);
            __stcs(Opt + (size_t)u * N, ov);
        }
    }

    #pragma unroll
    for (int u = 0; u < UNROLL; ++u) {
        int row = t + u;
        if (row < T) {
            float It = buf[u];
            int tt = row + UNROLL;
            float nx = (tt < T) ? __ldcs(Ip + (size_t)tt * N) : 0.0f;
            float ov;
            adex_step(It, v, c, p1, p2, ov);
            __stcs(Op + (size_t)row * N, ov);
            buf[u] = nx;
        }
    }
    t += UNROLL;

    #pragma unroll
    for (int u = 0; u < UNROLL; ++u) {
        int row = t + u;
        if (row < T) {
            float ov;
            adex_step(buf[u], v, c, p1, p2, ov);
            __stcs(Op + (size_t)row * N, ov);
        }
    }
}

extern "C" void kernel_launch(void* const* d_in, const int* in_sizes, int n_in,
                              void* d_out, int out_size)
{
    const float* I    = (const float*)d_in[0];
    const float* v0   = (const float*)d_in[1];
    const float* c0   = (const float*)d_in[2];
    const int*   ref0 = (const int*)  d_in[3];
    float*       out  = (float*)d_out;

    int N = in_sizes[1];
    int T = in_sizes[0] / N;

    int threads = 256;
    int blocks  = (N + threads - 1) / threads;

    if (N == 100000) {
        adex_kernel<100000><<<blocks, threads>>>(I, v0, c0, ref0, out, T, N);
    } else {
        adex_kernel<0><<<blocks, threads>>>(I, v0, c0, ref0, out, T, N);
    }
}